// round 4
// baseline (speedup 1.0000x reference)
#include <cuda_runtime.h>

#define E 8
#define NBLK 1184          // 148 SMs * 8
#define NTHR 256
#define NWARP (NTHR / 32)

// Per-block partial results: written (not accumulated) every run -> deterministic,
// no init pass needed.
__device__ float g_psp[NBLK][E];
__device__ float g_pct[NBLK][E];
__device__ unsigned int g_counter;   // zero-init at load; last block resets to 0 each run

__device__ __forceinline__ void process_token(const float4 a, const float4 b,
                                              float* sp, unsigned long long& cnt) {
    float x[E] = {a.x, a.y, a.z, a.w, b.x, b.y, b.z, b.w};

    // softmax terms (logits ~ N(0,1): no overflow without max-subtraction)
    float ex[E];
#pragma unroll
    for (int e = 0; e < E; e++) ex[e] = __expf(x[e]);
    float s = ((ex[0] + ex[1]) + (ex[2] + ex[3])) + ((ex[4] + ex[5]) + (ex[6] + ex[7]));
    float inv;
    asm("rcp.approx.f32 %0, %1;" : "=f"(inv) : "f"(s));
#pragma unroll
    for (int e = 0; e < E; e++) sp[e] = fmaf(ex[e], inv, sp[e]);

    // top-2 indices on logits (softmax monotone). Strict-> ascending scan matches
    // jax.lax.top_k lowest-index tie-break.
    int i1 = 0; float m1 = x[0];
#pragma unroll
    for (int e = 1; e < E; e++) { if (x[e] > m1) { m1 = x[e]; i1 = e; } }
    int i2 = (i1 == 0) ? 1 : 0; float m2 = x[i2];
#pragma unroll
    for (int e = 0; e < E; e++) { if (e != i1 && x[e] > m2) { m2 = x[e]; i2 = e; } }

    // packed 8x8-bit counters: max 14 tokens/thread, each byte +<=1/token -> no overflow
    cnt += (1ull << (8 * i1)) + (1ull << (8 * i2));
}

__global__ void __launch_bounds__(NTHR) router_fused_kernel(
    const float4* __restrict__ in, float* __restrict__ out, int num_tokens)
{
    const int tid    = blockIdx.x * NTHR + threadIdx.x;
    const int stride = NBLK * NTHR;

    float sp[E];
#pragma unroll
    for (int e = 0; e < E; e++) sp[e] = 0.0f;
    unsigned long long cnt = 0;

    int t = tid;
    // Unrolled-by-4: 8 independent LDG.128 front-batched -> MLP ~8
    for (; t + 3 * stride < num_tokens; t += 4 * stride) {
        const int t1 = t + stride, t2 = t + 2 * stride, t3 = t + 3 * stride;
        float4 a0 = in[2 * t],  b0 = in[2 * t + 1];
        float4 a1 = in[2 * t1], b1 = in[2 * t1 + 1];
        float4 a2 = in[2 * t2], b2 = in[2 * t2 + 1];
        float4 a3 = in[2 * t3], b3 = in[2 * t3 + 1];
        process_token(a0, b0, sp, cnt);
        process_token(a1, b1, sp, cnt);
        process_token(a2, b2, sp, cnt);
        process_token(a3, b3, sp, cnt);
    }
    for (; t < num_tokens; t += stride) {
        float4 a = in[2 * t], b = in[2 * t + 1];
        process_token(a, b, sp, cnt);
    }

    // unpack packed counters to floats
    float ct[E];
#pragma unroll
    for (int e = 0; e < E; e++) ct[e] = (float)((cnt >> (8 * e)) & 0xFFull);

    // warp reduction
#pragma unroll
    for (int e = 0; e < E; e++) {
#pragma unroll
        for (int off = 16; off > 0; off >>= 1) {
            sp[e] += __shfl_down_sync(0xffffffffu, sp[e], off);
            ct[e] += __shfl_down_sync(0xffffffffu, ct[e], off);
        }
    }

    // cross-warp reduction via shared, then write per-block partials
    __shared__ float sred[NWARP][2 * E];
    const int wid = threadIdx.x >> 5, lane = threadIdx.x & 31;
    if (lane == 0) {
#pragma unroll
        for (int e = 0; e < E; e++) { sred[wid][e] = sp[e]; sred[wid][E + e] = ct[e]; }
    }
    __syncthreads();
    if (threadIdx.x < 2 * E) {
        float v = 0.0f;
#pragma unroll
        for (int w = 0; w < NWARP; w++) v += sred[w][threadIdx.x];
        if (threadIdx.x < E) g_psp[blockIdx.x][threadIdx.x]     = v;
        else                 g_pct[blockIdx.x][threadIdx.x - E] = v;
    }

    // ---- last-block final reduction (threadfence pattern) ----
    __shared__ bool is_last;
    __threadfence();
    if (threadIdx.x == 0) {
        unsigned int prev = atomicAdd(&g_counter, 1u);
        is_last = (prev == (unsigned int)(NBLK - 1));
    }
    __syncthreads();
    if (!is_last) return;

    // 256 threads reduce 1184x8 partials (L2-hot). e = lane within expert group.
    const int e   = threadIdx.x & 7;
    const int idx = threadIdx.x >> 3;          // 0..31
    float fsp = 0.0f, fct = 0.0f;
    for (int b = idx; b < NBLK; b += 32) {     // coalesced: e fastest-varying
        fsp += g_psp[b][e];
        fct += g_pct[b][e];
    }

    __shared__ float s_sp[NTHR], s_ct[NTHR];
    s_sp[threadIdx.x] = fsp; s_ct[threadIdx.x] = fct;
    __syncthreads();
    // deterministic tree; strides multiple of 8 preserve expert lane
#pragma unroll
    for (int h = 128; h >= 8; h >>= 1) {
        if (threadIdx.x < h) {
            s_sp[threadIdx.x] += s_sp[threadIdx.x + h];
            s_ct[threadIdx.x] += s_ct[threadIdx.x + h];
        }
        __syncthreads();
    }

    if (threadIdx.x == 0) {
        double total = 0.0;
#pragma unroll
        for (int k = 0; k < E; k++)
            total += (double)s_ct[k] * (double)s_sp[k];
        double T = (double)num_tokens;
        out[0] = (float)(0.02 * (double)E * total / (T * T));
        g_counter = 0;   // reset for next run / graph replay
    }
}

extern "C" void kernel_launch(void* const* d_in, const int* in_sizes, int n_in,
                              void* d_out, int out_size) {
    const float4* in = (const float4*)d_in[0];
    float* out = (float*)d_out;
    int num_tokens = in_sizes[0] / E;

    router_fused_kernel<<<NBLK, NTHR>>>(in, out, num_tokens);
}

// round 5
// speedup vs baseline: 1.0073x; 1.0073x over previous
#include <cuda_runtime.h>

#define E 8
#define NBLK 1184          // 148 SMs * 8
#define NTHR 256
#define NWARP (NTHR / 32)

// Per-block partial results: written (not accumulated) every run -> deterministic,
// no init pass needed.
__device__ float g_psp[NBLK][E];
__device__ float g_pct[NBLK][E];
__device__ unsigned int g_counter;   // zero-init at load; last block resets to 0 each run

__device__ __forceinline__ void process_token(const float4 a, const float4 b,
                                              float* sp, unsigned long long& cnt) {
    float x[E] = {a.x, a.y, a.z, a.w, b.x, b.y, b.z, b.w};

    // softmax terms (logits ~ N(0,1): no overflow without max-subtraction)
    float ex[E];
#pragma unroll
    for (int e = 0; e < E; e++) ex[e] = __expf(x[e]);
    float s = ((ex[0] + ex[1]) + (ex[2] + ex[3])) + ((ex[4] + ex[5]) + (ex[6] + ex[7]));
    float inv;
    asm("rcp.approx.f32 %0, %1;" : "=f"(inv) : "f"(s));
#pragma unroll
    for (int e = 0; e < E; e++) sp[e] = fmaf(ex[e], inv, sp[e]);

    // top-2 indices on logits (softmax monotone). Strict-> ascending scan matches
    // jax.lax.top_k lowest-index tie-break.
    int i1 = 0; float m1 = x[0];
#pragma unroll
    for (int e = 1; e < E; e++) { if (x[e] > m1) { m1 = x[e]; i1 = e; } }
    int i2 = (i1 == 0) ? 1 : 0; float m2 = x[i2];
#pragma unroll
    for (int e = 0; e < E; e++) { if (e != i1 && x[e] > m2) { m2 = x[e]; i2 = e; } }

    // packed 8x8-bit counters: max 14 tokens/thread, each byte +<=1/token -> no overflow
    cnt += (1ull << (8 * i1)) + (1ull << (8 * i2));
}

__global__ void __launch_bounds__(NTHR) router_fused_kernel(
    const float4* __restrict__ in, float* __restrict__ out, int num_tokens)
{
    const int tid    = blockIdx.x * NTHR + threadIdx.x;
    const int stride = NBLK * NTHR;

    float sp[E];
#pragma unroll
    for (int e = 0; e < E; e++) sp[e] = 0.0f;
    unsigned long long cnt = 0;

    int t = tid;
    // Unrolled-by-4: 8 independent LDG.128 front-batched -> MLP ~8
    for (; t + 3 * stride < num_tokens; t += 4 * stride) {
        const int t1 = t + stride, t2 = t + 2 * stride, t3 = t + 3 * stride;
        float4 a0 = in[2 * t],  b0 = in[2 * t + 1];
        float4 a1 = in[2 * t1], b1 = in[2 * t1 + 1];
        float4 a2 = in[2 * t2], b2 = in[2 * t2 + 1];
        float4 a3 = in[2 * t3], b3 = in[2 * t3 + 1];
        process_token(a0, b0, sp, cnt);
        process_token(a1, b1, sp, cnt);
        process_token(a2, b2, sp, cnt);
        process_token(a3, b3, sp, cnt);
    }
    for (; t < num_tokens; t += stride) {
        float4 a = in[2 * t], b = in[2 * t + 1];
        process_token(a, b, sp, cnt);
    }

    // unpack packed counters to floats
    float ct[E];
#pragma unroll
    for (int e = 0; e < E; e++) ct[e] = (float)((cnt >> (8 * e)) & 0xFFull);

    // warp reduction
#pragma unroll
    for (int e = 0; e < E; e++) {
#pragma unroll
        for (int off = 16; off > 0; off >>= 1) {
            sp[e] += __shfl_down_sync(0xffffffffu, sp[e], off);
            ct[e] += __shfl_down_sync(0xffffffffu, ct[e], off);
        }
    }

    // cross-warp reduction via shared, then write per-block partials
    __shared__ float sred[NWARP][2 * E];
    const int wid = threadIdx.x >> 5, lane = threadIdx.x & 31;
    if (lane == 0) {
#pragma unroll
        for (int e = 0; e < E; e++) { sred[wid][e] = sp[e]; sred[wid][E + e] = ct[e]; }
    }
    __syncthreads();
    if (threadIdx.x < 2 * E) {
        float v = 0.0f;
#pragma unroll
        for (int w = 0; w < NWARP; w++) v += sred[w][threadIdx.x];
        if (threadIdx.x < E) g_psp[blockIdx.x][threadIdx.x]     = v;
        else                 g_pct[blockIdx.x][threadIdx.x - E] = v;
    }

    // ---- last-block final reduction (threadfence pattern) ----
    __shared__ bool is_last;
    __threadfence();
    if (threadIdx.x == 0) {
        unsigned int prev = atomicAdd(&g_counter, 1u);
        is_last = (prev == (unsigned int)(NBLK - 1));
    }
    __syncthreads();
    if (!is_last) return;

    // 256 threads reduce 1184x8 partials (L2-hot). e = lane within expert group.
    const int e   = threadIdx.x & 7;
    const int idx = threadIdx.x >> 3;          // 0..31
    float fsp = 0.0f, fct = 0.0f;
    for (int b = idx; b < NBLK; b += 32) {     // coalesced: e fastest-varying
        fsp += g_psp[b][e];
        fct += g_pct[b][e];
    }

    __shared__ float s_sp[NTHR], s_ct[NTHR];
    s_sp[threadIdx.x] = fsp; s_ct[threadIdx.x] = fct;
    __syncthreads();
    // deterministic tree; strides multiple of 8 preserve expert lane
#pragma unroll
    for (int h = 128; h >= 8; h >>= 1) {
        if (threadIdx.x < h) {
            s_sp[threadIdx.x] += s_sp[threadIdx.x + h];
            s_ct[threadIdx.x] += s_ct[threadIdx.x + h];
        }
        __syncthreads();
    }

    if (threadIdx.x == 0) {
        double total = 0.0;
#pragma unroll
        for (int k = 0; k < E; k++)
            total += (double)s_ct[k] * (double)s_sp[k];
        double T = (double)num_tokens;
        out[0] = (float)(0.02 * (double)E * total / (T * T));
        g_counter = 0;   // reset for next run / graph replay
    }
}

extern "C" void kernel_launch(void* const* d_in, const int* in_sizes, int n_in,
                              void* d_out, int out_size) {
    const float4* in = (const float4*)d_in[0];
    float* out = (float*)d_out;
    int num_tokens = in_sizes[0] / E;

    router_fused_kernel<<<NBLK, NTHR>>>(in, out, num_tokens);
}

// round 6
// speedup vs baseline: 1.1251x; 1.1170x over previous
#include <cuda_runtime.h>

#define E 8
#define NBLK 1184          // 148 SMs * 8
#define NTHR 256
#define NWARP (NTHR / 32)

// Per-block partial results: written (not accumulated) every run -> deterministic.
__device__ float g_psp[NBLK][E];
__device__ float g_pct[NBLK][E];
__device__ unsigned int g_counter;   // zero-init at load; last block resets each run

__device__ __forceinline__ void process_token(const float4 a, const float4 b,
                                              float* sp, float* ct) {
    float x[E] = {a.x, a.y, a.z, a.w, b.x, b.y, b.z, b.w};

    // softmax terms (logits ~ N(0,1): no overflow without max-subtraction)
    float ex[E];
#pragma unroll
    for (int e = 0; e < E; e++) ex[e] = __expf(x[e]);
    float s = ((ex[0] + ex[1]) + (ex[2] + ex[3])) + ((ex[4] + ex[5]) + (ex[6] + ex[7]));
    float inv;
    asm("rcp.approx.f32 %0, %1;" : "=f"(inv) : "f"(s));
#pragma unroll
    for (int e = 0; e < E; e++) sp[e] = fmaf(ex[e], inv, sp[e]);

    // ---- second-max via predicate-free FMNMX tournament ----
    // Each subtree carries its top-2 (hi, lo).
    // Merge identity: second(union) = max( min(a_hi,b_hi), a_lo, b_lo ).
    float h0 = fmaxf(x[0], x[1]), l0 = fminf(x[0], x[1]);
    float h1 = fmaxf(x[2], x[3]), l1 = fminf(x[2], x[3]);
    float h2 = fmaxf(x[4], x[5]), l2 = fminf(x[4], x[5]);
    float h3 = fmaxf(x[6], x[7]), l3 = fminf(x[6], x[7]);

    float ha = fmaxf(h0, h1);
    float la = fmaxf(fminf(h0, h1), fmaxf(l0, l1));
    float hb = fmaxf(h2, h3);
    float lb = fmaxf(fminf(h2, h3), fmaxf(l2, l3));

    float m2 = fmaxf(fminf(ha, hb), fmaxf(la, lb));  // global 2nd max (hi not needed)

    // expert in top-2  <=>  x[e] >= m2  (exact ties over-count, effect ~1e-6 in loss)
#pragma unroll
    for (int e = 0; e < E; e++)
        ct[e] += (x[e] >= m2) ? 1.0f : 0.0f;
}

__global__ void __launch_bounds__(NTHR) router_fused_kernel(
    const float4* __restrict__ in, float* __restrict__ out, int num_tokens)
{
    const int tid    = blockIdx.x * NTHR + threadIdx.x;
    const int stride = NBLK * NTHR;

    float sp[E], ct[E];
#pragma unroll
    for (int e = 0; e < E; e++) { sp[e] = 0.0f; ct[e] = 0.0f; }

    int t = tid;
    // Unrolled-by-4: 8 independent LDG.128 front-batched -> MLP ~8
    for (; t + 3 * stride < num_tokens; t += 4 * stride) {
        const int t1 = t + stride, t2 = t + 2 * stride, t3 = t + 3 * stride;
        float4 a0 = in[2 * t],  b0 = in[2 * t + 1];
        float4 a1 = in[2 * t1], b1 = in[2 * t1 + 1];
        float4 a2 = in[2 * t2], b2 = in[2 * t2 + 1];
        float4 a3 = in[2 * t3], b3 = in[2 * t3 + 1];
        process_token(a0, b0, sp, ct);
        process_token(a1, b1, sp, ct);
        process_token(a2, b2, sp, ct);
        process_token(a3, b3, sp, ct);
    }
    for (; t < num_tokens; t += stride) {
        float4 a = in[2 * t], b = in[2 * t + 1];
        process_token(a, b, sp, ct);
    }

    // warp reduction
#pragma unroll
    for (int e = 0; e < E; e++) {
#pragma unroll
        for (int off = 16; off > 0; off >>= 1) {
            sp[e] += __shfl_down_sync(0xffffffffu, sp[e], off);
            ct[e] += __shfl_down_sync(0xffffffffu, ct[e], off);
        }
    }

    // cross-warp reduction via shared, then write per-block partials
    __shared__ float sred[NWARP][2 * E];
    const int wid = threadIdx.x >> 5, lane = threadIdx.x & 31;
    if (lane == 0) {
#pragma unroll
        for (int e = 0; e < E; e++) { sred[wid][e] = sp[e]; sred[wid][E + e] = ct[e]; }
    }
    __syncthreads();
    if (threadIdx.x < 2 * E) {
        float v = 0.0f;
#pragma unroll
        for (int w = 0; w < NWARP; w++) v += sred[w][threadIdx.x];
        if (threadIdx.x < E) g_psp[blockIdx.x][threadIdx.x]     = v;
        else                 g_pct[blockIdx.x][threadIdx.x - E] = v;
    }

    // ---- last-block final reduction (threadfence pattern) ----
    __shared__ bool is_last;
    __threadfence();
    if (threadIdx.x == 0) {
        unsigned int prev = atomicAdd(&g_counter, 1u);
        is_last = (prev == (unsigned int)(NBLK - 1));
    }
    __syncthreads();
    if (!is_last) return;

    // 256 threads reduce 1184x8 partials (L2-hot). e = lane within expert group.
    const int e   = threadIdx.x & 7;
    const int idx = threadIdx.x >> 3;          // 0..31
    float fsp = 0.0f, fct = 0.0f;
    for (int b = idx; b < NBLK; b += 32) {     // coalesced: e fastest-varying
        fsp += g_psp[b][e];
        fct += g_pct[b][e];
    }

    __shared__ float s_sp[NTHR], s_ct[NTHR];
    s_sp[threadIdx.x] = fsp; s_ct[threadIdx.x] = fct;
    __syncthreads();
    // deterministic tree; strides multiple of 8 preserve expert lane
#pragma unroll
    for (int h = 128; h >= 8; h >>= 1) {
        if (threadIdx.x < h) {
            s_sp[threadIdx.x] += s_sp[threadIdx.x + h];
            s_ct[threadIdx.x] += s_ct[threadIdx.x + h];
        }
        __syncthreads();
    }

    if (threadIdx.x == 0) {
        double total = 0.0;
#pragma unroll
        for (int k = 0; k < E; k++)
            total += (double)s_ct[k] * (double)s_sp[k];
        double T = (double)num_tokens;
        out[0] = (float)(0.02 * (double)E * total / (T * T));
        g_counter = 0;   // reset for next run / graph replay
    }
}

extern "C" void kernel_launch(void* const* d_in, const int* in_sizes, int n_in,
                              void* d_out, int out_size) {
    const float4* in = (const float4*)d_in[0];
    float* out = (float*)d_out;
    int num_tokens = in_sizes[0] / E;

    router_fused_kernel<<<NBLK, NTHR>>>(in, out, num_tokens);
}

// round 7
// speedup vs baseline: 1.2573x; 1.1175x over previous
#include <cuda_runtime.h>

#define E 8
#define NBLK 740           // 148 SMs * 5 -> exactly one wave at 5 blocks/SM
#define NTHR 256
#define NWARP (NTHR / 32)

// Per-block partial results: written (not accumulated) every run -> deterministic.
__device__ float g_psp[NBLK][E];
__device__ float g_pct[NBLK][E];
__device__ unsigned int g_counter;   // zero-init at load; last block resets each run

__device__ __forceinline__ void process_token(const float4 a, const float4 b,
                                              float* sp,
                                              unsigned int& cnt0, unsigned int& cnt1) {
    float x[E] = {a.x, a.y, a.z, a.w, b.x, b.y, b.z, b.w};

    // softmax terms (logits ~ N(0,1): no overflow without max-subtraction)
    float ex[E];
#pragma unroll
    for (int e = 0; e < E; e++) ex[e] = __expf(x[e]);
    float s = ((ex[0] + ex[1]) + (ex[2] + ex[3])) + ((ex[4] + ex[5]) + (ex[6] + ex[7]));
    float inv;
    asm("rcp.approx.f32 %0, %1;" : "=f"(inv) : "f"(s));
#pragma unroll
    for (int e = 0; e < E; e++) sp[e] = fmaf(ex[e], inv, sp[e]);

    // ---- second-max via predicate-free FMNMX tournament ----
    // Merge identity: second(union) = max( min(a_hi,b_hi), a_lo, b_lo ).
    float h0 = fmaxf(x[0], x[1]), l0 = fminf(x[0], x[1]);
    float h1 = fmaxf(x[2], x[3]), l1 = fminf(x[2], x[3]);
    float h2 = fmaxf(x[4], x[5]), l2 = fminf(x[4], x[5]);
    float h3 = fmaxf(x[6], x[7]), l3 = fminf(x[6], x[7]);

    float ha = fmaxf(h0, h1);
    float la = fmaxf(fminf(h0, h1), fmaxf(l0, l1));
    float hb = fmaxf(h2, h3);
    float lb = fmaxf(fminf(h2, h3), fmaxf(l2, l3));

    float m2 = fmaxf(fminf(ha, hb), fmaxf(la, lb));  // global 2nd max

    // expert in top-2  <=>  x[e] >= m2.
    // Packed 4x8-bit counters per u32; e is compile-time -> immediate IADD, predicated.
    // Max ~23 tokens/thread, each byte +<=1/token -> no overflow.
#pragma unroll
    for (int e = 0; e < 4; e++)
        if (x[e] >= m2) cnt0 += (1u << (8 * e));
#pragma unroll
    for (int e = 4; e < 8; e++)
        if (x[e] >= m2) cnt1 += (1u << (8 * (e - 4)));
}

__global__ void __launch_bounds__(NTHR, 5) router_fused_kernel(
    const float4* __restrict__ in, float* __restrict__ out, int num_tokens)
{
    const int tid    = blockIdx.x * NTHR + threadIdx.x;
    const int stride = NBLK * NTHR;

    float sp[E];
#pragma unroll
    for (int e = 0; e < E; e++) sp[e] = 0.0f;
    unsigned int cnt0 = 0, cnt1 = 0;

    int t = tid;
    // Unrolled-by-4: 8 independent LDG.128 front-batched -> MLP ~8
    for (; t + 3 * stride < num_tokens; t += 4 * stride) {
        const int t1 = t + stride, t2 = t + 2 * stride, t3 = t + 3 * stride;
        float4 a0 = in[2 * t],  b0 = in[2 * t + 1];
        float4 a1 = in[2 * t1], b1 = in[2 * t1 + 1];
        float4 a2 = in[2 * t2], b2 = in[2 * t2 + 1];
        float4 a3 = in[2 * t3], b3 = in[2 * t3 + 1];
        process_token(a0, b0, sp, cnt0, cnt1);
        process_token(a1, b1, sp, cnt0, cnt1);
        process_token(a2, b2, sp, cnt0, cnt1);
        process_token(a3, b3, sp, cnt0, cnt1);
    }
    for (; t < num_tokens; t += stride) {
        float4 a = in[2 * t], b = in[2 * t + 1];
        process_token(a, b, sp, cnt0, cnt1);
    }

    // unpack packed counters to floats
    float ct[E];
#pragma unroll
    for (int e = 0; e < 4; e++) ct[e]     = (float)((cnt0 >> (8 * e)) & 0xFFu);
#pragma unroll
    for (int e = 0; e < 4; e++) ct[4 + e] = (float)((cnt1 >> (8 * e)) & 0xFFu);

    // warp reduction
#pragma unroll
    for (int e = 0; e < E; e++) {
#pragma unroll
        for (int off = 16; off > 0; off >>= 1) {
            sp[e] += __shfl_down_sync(0xffffffffu, sp[e], off);
            ct[e] += __shfl_down_sync(0xffffffffu, ct[e], off);
        }
    }

    // cross-warp reduction via shared, then write per-block partials
    __shared__ float sred[NWARP][2 * E];
    const int wid = threadIdx.x >> 5, lane = threadIdx.x & 31;
    if (lane == 0) {
#pragma unroll
        for (int e = 0; e < E; e++) { sred[wid][e] = sp[e]; sred[wid][E + e] = ct[e]; }
    }
    __syncthreads();
    if (threadIdx.x < 2 * E) {
        float v = 0.0f;
#pragma unroll
        for (int w = 0; w < NWARP; w++) v += sred[w][threadIdx.x];
        if (threadIdx.x < E) g_psp[blockIdx.x][threadIdx.x]     = v;
        else                 g_pct[blockIdx.x][threadIdx.x - E] = v;
    }

    // ---- last-block final reduction (threadfence pattern) ----
    __shared__ bool is_last;
    __threadfence();
    if (threadIdx.x == 0) {
        unsigned int prev = atomicAdd(&g_counter, 1u);
        is_last = (prev == (unsigned int)(NBLK - 1));
    }
    __syncthreads();
    if (!is_last) return;

    // 256 threads reduce 740x8 partials (L2-hot). e = lane within expert group.
    const int e   = threadIdx.x & 7;
    const int idx = threadIdx.x >> 3;          // 0..31
    float fsp = 0.0f, fct = 0.0f;
    for (int b = idx; b < NBLK; b += 32) {     // coalesced: e fastest-varying
        fsp += g_psp[b][e];
        fct += g_pct[b][e];
    }

    __shared__ float s_sp[NTHR], s_ct[NTHR];
    s_sp[threadIdx.x] = fsp; s_ct[threadIdx.x] = fct;
    __syncthreads();
    // deterministic tree; strides multiple of 8 preserve expert lane
#pragma unroll
    for (int h = 128; h >= 8; h >>= 1) {
        if (threadIdx.x < h) {
            s_sp[threadIdx.x] += s_sp[threadIdx.x + h];
            s_ct[threadIdx.x] += s_ct[threadIdx.x + h];
        }
        __syncthreads();
    }

    if (threadIdx.x == 0) {
        double total = 0.0;
#pragma unroll
        for (int k = 0; k < E; k++)
            total += (double)s_ct[k] * (double)s_sp[k];
        double T = (double)num_tokens;
        out[0] = (float)(0.02 * (double)E * total / (T * T));
        g_counter = 0;   // reset for next run / graph replay
    }
}

extern "C" void kernel_launch(void* const* d_in, const int* in_sizes, int n_in,
                              void* d_out, int out_size) {
    const float4* in = (const float4*)d_in[0];
    float* out = (float*)d_out;
    int num_tokens = in_sizes[0] / E;

    router_fused_kernel<<<NBLK, NTHR>>>(in, out, num_tokens);
}